// round 4
// baseline (speedup 1.0000x reference)
#include <cuda_runtime.h>
#include <cstdint>

#define N_NODES 50000
#define HID     256
#define NH      (N_NODES * HID)

// ---------------- scratch (static device globals; no allocation) ------------
__device__ float g_buf1[NH];      // t = A@x, later p = A@h
__device__ float g_buf2[NH];      // h
__device__ float g_dinv[N_NODES];
__device__ int   g_deg[N_NODES];

// ---------------- degree / norm --------------------------------------------
__global__ void k_zero_deg() {
    int i = blockIdx.x * blockDim.x + threadIdx.x;
    if (i < N_NODES) g_deg[i] = 0;
}

__global__ void k_count_deg(const int* __restrict__ ei, int E) {
    int i = blockIdx.x * blockDim.x + threadIdx.x;
    if (i < E) atomicAdd(&g_deg[ei[E + i]], 1);
}

__global__ void k_dinv() {
    int i = blockIdx.x * blockDim.x + threadIdx.x;
    if (i < N_NODES) g_dinv[i] = rsqrtf((float)(g_deg[i] + 1));  // +1 self loop
}

// ---------------- self-loop init: Y = dinv[i]^2 * X[i] ----------------------
__global__ void k_selfloop(const float* __restrict__ X, float* __restrict__ Y) {
    int i = blockIdx.x * blockDim.x + threadIdx.x;     // over NH/4 float4s
    if (i < NH / 4) {
        int row = i >> 6;                              // 64 float4 per row
        float w = g_dinv[row];
        w *= w;
        float4 v = ((const float4*)X)[i];
        v.x *= w; v.y *= w; v.z *= w; v.w *= w;
        ((float4*)Y)[i] = v;
    }
}

// ---------------- edge scatter SpMM: Y[dst] += dinv[s]*dinv[d] * X[src] -----
// one warp per edge; 2x float4 per lane covers 256 columns
__global__ void k_spmm_edges(const int* __restrict__ ei,
                             const float* __restrict__ X,
                             float* __restrict__ Y, int E) {
    int gt = blockIdx.x * blockDim.x + threadIdx.x;
    int warp = gt >> 5;
    int lane = gt & 31;
    if (warp >= E) return;
    int s = __ldg(&ei[warp]);
    int d = __ldg(&ei[E + warp]);
    float w = g_dinv[s] * g_dinv[d];
    const float4* xs = (const float4*)(X + (size_t)s * HID);
    float4*       yd = (float4*)(Y + (size_t)d * HID);
#pragma unroll
    for (int i = 0; i < 2; i++) {
        float4 v = __ldg(xs + lane + 32 * i);
        asm volatile("red.global.add.v4.f32 [%0], {%1, %2, %3, %4};"
                     :: "l"(yd + lane + 32 * i),
                        "f"(v.x * w), "f"(v.y * w), "f"(v.z * w), "f"(v.w * w)
                     : "memory");
    }
}

// ---------------- SGEMM: C = act(A[M,K] @ B[K,N] + bias) --------------------
// 128x128 block tile, BK=8, 256 threads, 8x8 per thread
__global__ void __launch_bounds__(256)
k_gemm(const float* __restrict__ A, const float* __restrict__ B,
       const float* __restrict__ bias, float* __restrict__ C,
       int M, int N, int K, int do_relu) {
    const int BM = 128, BN = 128, BK = 8;
    __shared__ float As[BK][BM];
    __shared__ float Bs[BK][BN];

    int tid = threadIdx.x;
    int rowBase = blockIdx.y * BM;
    int colBase = blockIdx.x * BN;

    int arow = tid >> 1, acol = (tid & 1) * 4;    // A tile load: 128 rows x 8 cols
    int brow = tid >> 5, bcol = (tid & 31) * 4;   // B tile load: 8 rows x 128 cols
    int tr = tid >> 4, tc = tid & 15;             // 16x16 thread grid, 8x8 each

    float acc[8][8];
#pragma unroll
    for (int i = 0; i < 8; i++)
#pragma unroll
        for (int j = 0; j < 8; j++) acc[i][j] = 0.f;

    for (int kt = 0; kt < K; kt += BK) {
        float4 av = make_float4(0.f, 0.f, 0.f, 0.f);
        int garow = rowBase + arow;
        if (garow < M)
            av = *(const float4*)(A + (size_t)garow * K + kt + acol);
        As[acol + 0][arow] = av.x;
        As[acol + 1][arow] = av.y;
        As[acol + 2][arow] = av.z;
        As[acol + 3][arow] = av.w;

        float4 bv = *(const float4*)(B + (size_t)(kt + brow) * N + colBase + bcol);
        *(float4*)&Bs[brow][bcol] = bv;
        __syncthreads();

#pragma unroll
        for (int k = 0; k < BK; k++) {
            float ra[8], rb[8];
            *(float4*)&ra[0] = *(float4*)&As[k][tr * 8];
            *(float4*)&ra[4] = *(float4*)&As[k][tr * 8 + 4];
            *(float4*)&rb[0] = *(float4*)&Bs[k][tc * 8];
            *(float4*)&rb[4] = *(float4*)&Bs[k][tc * 8 + 4];
#pragma unroll
            for (int i = 0; i < 8; i++)
#pragma unroll
                for (int j = 0; j < 8; j++) acc[i][j] += ra[i] * rb[j];
        }
        __syncthreads();
    }

    float rbias[8];
#pragma unroll
    for (int j = 0; j < 8; j++) rbias[j] = bias[colBase + tc * 8 + j];

#pragma unroll
    for (int i = 0; i < 8; i++) {
        int row = rowBase + tr * 8 + i;
        if (row >= M) continue;
        float* cptr = C + (size_t)row * N + colBase + tc * 8;
#pragma unroll
        for (int j4 = 0; j4 < 2; j4++) {
            float4 v;
            v.x = acc[i][j4 * 4 + 0] + rbias[j4 * 4 + 0];
            v.y = acc[i][j4 * 4 + 1] + rbias[j4 * 4 + 1];
            v.z = acc[i][j4 * 4 + 2] + rbias[j4 * 4 + 2];
            v.w = acc[i][j4 * 4 + 3] + rbias[j4 * 4 + 3];
            if (do_relu) {
                v.x = fmaxf(v.x, 0.f); v.y = fmaxf(v.y, 0.f);
                v.z = fmaxf(v.z, 0.f); v.w = fmaxf(v.w, 0.f);
            }
            *(float4*)(cptr + j4 * 4) = v;
        }
    }
}

// ---------------- threefry2x32 (JAX-exact) ----------------------------------
__device__ __forceinline__ uint32_t tf_rotl(uint32_t v, int s) {
    return (v << s) | (v >> (32 - s));
}

__device__ __forceinline__ uint2 threefry2x32(uint32_t k0, uint32_t k1,
                                              uint32_t x0, uint32_t x1) {
    uint32_t ks2 = k0 ^ k1 ^ 0x1BD11BDAu;
    x0 += k0; x1 += k1;
#define TF_R(r) { x0 += x1; x1 = tf_rotl(x1, r); x1 ^= x0; }
    TF_R(13) TF_R(15) TF_R(26) TF_R(6)   x0 += k1;  x1 += ks2 + 1u;
    TF_R(17) TF_R(29) TF_R(16) TF_R(24)  x0 += ks2; x1 += k0 + 2u;
    TF_R(13) TF_R(15) TF_R(26) TF_R(6)   x0 += k0;  x1 += k1 + 3u;
    TF_R(17) TF_R(29) TF_R(16) TF_R(24)  x0 += k1;  x1 += ks2 + 4u;
    TF_R(13) TF_R(15) TF_R(26) TF_R(6)   x0 += ks2; x1 += k0 + 5u;
#undef TF_R
    return make_uint2(x0, x1);
}

__device__ __forceinline__ float bits_to_eps(uint32_t bits) {
    // jax.random.normal: u ~ uniform(nextafter(-1,0), 1); eps = sqrt(2)*erfinv(u)
    float u01 = __uint_as_float((bits >> 9) | 0x3f800000u) - 1.0f;
    const float lo = __uint_as_float(0xBF7FFFFFu);   // nextafter(-1f, 0f)
    const float span = 1.0f - lo;                    // 1.9999999404f
    float v = __fadd_rn(__fmul_rn(u01, span), lo);
    v = fmaxf(lo, v);
    return 1.41421356f * erfinvf(v);
}

// ---------------- z = mu + exp(logstd) * eps --------------------------------
// JAX threefry_partitionable random_bits (default since 0.4.36):
//   counts = iota(uint64, n); bits1, bits2 = threefry2x32(key, (hi, lo));
//   bits = bits1 ^ bits2
__global__ void k_z(const float* __restrict__ mu, const float* __restrict__ ls,
                    float* __restrict__ z, int total) {
    int i = blockIdx.x * blockDim.x + threadIdx.x;
    if (i >= total) return;
    uint2 r = threefry2x32(0u, 1u, 0u, (uint32_t)i);   // hi(i)=0 for n < 2^32
    uint32_t bits = r.x ^ r.y;                          // <-- the XOR fold
    float eps = bits_to_eps(bits);
    z[i] = mu[i] + expf(ls[i]) * eps;
}

// ---------------- launch -----------------------------------------------------
extern "C" void kernel_launch(void* const* d_in, const int* in_sizes, int n_in,
                              void* d_out, int out_size) {
    const float* x   = (const float*)d_in[0];
    const int*   ei  = (const int*)d_in[1];   // JAX default x64-disabled: int32
    const float* W1  = (const float*)d_in[2];
    const float* b1  = (const float*)d_in[3];
    const float* Wmu = (const float*)d_in[4];
    const float* bmu = (const float*)d_in[5];
    const float* Wls = (const float*)d_in[6];
    const float* bls = (const float*)d_in[7];
    int E = in_sizes[1] / 2;

    float* out = (float*)d_out;
    float* z   = out;
    float* mu  = out + (size_t)NH;
    float* ls  = out + 2 * (size_t)NH;

    float* buf1; float* buf2;
    cudaGetSymbolAddress((void**)&buf1, g_buf1);
    cudaGetSymbolAddress((void**)&buf2, g_buf2);

    // degrees + norm
    k_zero_deg<<<(N_NODES + 255) / 256, 256>>>();
    k_count_deg<<<(E + 255) / 256, 256>>>(ei, E);
    k_dinv<<<(N_NODES + 255) / 256, 256>>>();

    // t = A_norm @ x  -> buf1
    k_selfloop<<<(NH / 4 + 255) / 256, 256>>>(x, buf1);
    {
        long long thr = (long long)E * 32;
        k_spmm_edges<<<(unsigned)((thr + 255) / 256), 256>>>(ei, x, buf1, E);
    }

    // h = relu(t @ W1 + b1) -> buf2
    dim3 g1(HID / 128, (N_NODES + 127) / 128);
    k_gemm<<<g1, 256>>>(buf1, W1, b1, buf2, N_NODES, HID, HID, 1);

    // p = A_norm @ h -> buf1
    k_selfloop<<<(NH / 4 + 255) / 256, 256>>>(buf2, buf1);
    {
        long long thr = (long long)E * 32;
        k_spmm_edges<<<(unsigned)((thr + 255) / 256), 256>>>(ei, buf2, buf1, E);
    }

    // mu / logstd
    k_gemm<<<g1, 256>>>(buf1, Wmu, bmu, mu, N_NODES, HID, HID, 0);
    k_gemm<<<g1, 256>>>(buf1, Wls, bls, ls, N_NODES, HID, HID, 0);

    // z = mu + exp(logstd) * eps
    k_z<<<(NH + 255) / 256, 256>>>(mu, ls, z, NH);
}

// round 5
// speedup vs baseline: 1.2454x; 1.2454x over previous
#include <cuda_runtime.h>
#include <cstdint>

#define N_NODES 50000
#define HID     256
#define NH      (N_NODES * HID)
#define MAX_E   2000000

// ---------------- scratch (static device globals; no allocation) ------------
__device__ float g_buf1[NH];            // t = A@x, later p = A@h
__device__ float g_buf2[NH];            // h
__device__ float g_dinv[N_NODES];
__device__ int   g_deg[N_NODES];
__device__ int   g_rowptr[N_NODES + 1];
__device__ int   g_cur[N_NODES];
__device__ int   g_col[MAX_E];

// ---------------- degree / norm --------------------------------------------
__global__ void k_zero_deg() {
    int i = blockIdx.x * blockDim.x + threadIdx.x;
    if (i < N_NODES) g_deg[i] = 0;
}

__global__ void k_count_deg(const int* __restrict__ ei, int E) {
    int i = blockIdx.x * blockDim.x + threadIdx.x;
    if (i < E) atomicAdd(&g_deg[ei[E + i]], 1);
}

__global__ void k_dinv() {
    int i = blockIdx.x * blockDim.x + threadIdx.x;
    if (i < N_NODES) g_dinv[i] = rsqrtf((float)(g_deg[i] + 1));  // +1 self loop
}

// ---------------- exclusive scan of g_deg -> g_rowptr, g_cur (single block) --
__global__ void __launch_bounds__(1024) k_scan(int E) {
    __shared__ int sh[1024];
    __shared__ int carry_sh;
    int tid = threadIdx.x;
    if (tid == 0) carry_sh = 0;
    __syncthreads();
    for (int base = 0; base < N_NODES; base += 1024) {
        int i = base + tid;
        int v = (i < N_NODES) ? g_deg[i] : 0;
        sh[tid] = v;
        __syncthreads();
#pragma unroll
        for (int off = 1; off < 1024; off <<= 1) {
            int t = (tid >= off) ? sh[tid - off] : 0;
            __syncthreads();
            sh[tid] += t;
            __syncthreads();
        }
        int c = carry_sh;
        if (i < N_NODES) {
            int excl = c + sh[tid] - v;
            g_rowptr[i] = excl;
            g_cur[i] = excl;
        }
        __syncthreads();
        if (tid == 1023) carry_sh = c + sh[1023];
        __syncthreads();
    }
    if (tid == 0) g_rowptr[N_NODES] = E;
}

__global__ void k_fill(const int* __restrict__ ei, int E) {
    int e = blockIdx.x * blockDim.x + threadIdx.x;
    if (e < E) {
        int d = ei[E + e];
        int pos = atomicAdd(&g_cur[d], 1);
        g_col[pos] = ei[e];
    }
}

// ---------------- CSR SpMM: Y[d] = dd * sum_s dinv[s]*X[s] + dd^2 * X[d] ----
// one warp per node; each lane owns cols {lane, lane+32} as float4
__global__ void __launch_bounds__(256) k_spmm_csr(const float* __restrict__ X,
                                                  float* __restrict__ Y) {
    int node = blockIdx.x * 8 + (threadIdx.x >> 5);
    int lane = threadIdx.x & 31;
    if (node >= N_NODES) return;
    const float4* X4 = (const float4*)X;
    float4* Y4 = (float4*)Y;

    float4 s0 = make_float4(0.f, 0.f, 0.f, 0.f);
    float4 s1 = make_float4(0.f, 0.f, 0.f, 0.f);
    int beg = g_rowptr[node];
    int end = g_rowptr[node + 1];

    int e = beg;
    for (; e + 2 <= end; e += 2) {
        int sa = __ldg(&g_col[e]);
        int sb = __ldg(&g_col[e + 1]);
        float wa = g_dinv[sa];
        float wb = g_dinv[sb];
        const float4* pa = X4 + (size_t)sa * 64;
        const float4* pb = X4 + (size_t)sb * 64;
        float4 a0 = __ldg(pa + lane), a1 = __ldg(pa + lane + 32);
        float4 b0 = __ldg(pb + lane), b1 = __ldg(pb + lane + 32);
        s0.x += wa * a0.x + wb * b0.x; s0.y += wa * a0.y + wb * b0.y;
        s0.z += wa * a0.z + wb * b0.z; s0.w += wa * a0.w + wb * b0.w;
        s1.x += wa * a1.x + wb * b1.x; s1.y += wa * a1.y + wb * b1.y;
        s1.z += wa * a1.z + wb * b1.z; s1.w += wa * a1.w + wb * b1.w;
    }
    if (e < end) {
        int sa = __ldg(&g_col[e]);
        float wa = g_dinv[sa];
        const float4* pa = X4 + (size_t)sa * 64;
        float4 a0 = __ldg(pa + lane), a1 = __ldg(pa + lane + 32);
        s0.x += wa * a0.x; s0.y += wa * a0.y; s0.z += wa * a0.z; s0.w += wa * a0.w;
        s1.x += wa * a1.x; s1.y += wa * a1.y; s1.z += wa * a1.z; s1.w += wa * a1.w;
    }

    float dd = g_dinv[node];
    float dd2 = dd * dd;
    const float4* px = X4 + (size_t)node * 64;
    float4 x0 = __ldg(px + lane), x1 = __ldg(px + lane + 32);
    float4 o0, o1;
    o0.x = dd * s0.x + dd2 * x0.x; o0.y = dd * s0.y + dd2 * x0.y;
    o0.z = dd * s0.z + dd2 * x0.z; o0.w = dd * s0.w + dd2 * x0.w;
    o1.x = dd * s1.x + dd2 * x1.x; o1.y = dd * s1.y + dd2 * x1.y;
    o1.z = dd * s1.z + dd2 * x1.z; o1.w = dd * s1.w + dd2 * x1.w;
    Y4[(size_t)node * 64 + lane] = o0;
    Y4[(size_t)node * 64 + lane + 32] = o1;
}

// ---------------- packed f32x2 FMA helper -----------------------------------
__device__ __forceinline__ void fma2(unsigned long long& acc,
                                     unsigned long long a,
                                     unsigned long long b) {
    asm("fma.rn.f32x2 %0, %1, %2, %0;" : "+l"(acc) : "l"(a), "l"(b));
}

// ---------------- SGEMM (f32x2): C = act(A[M,256] @ B[256,256] + bias) ------
// 128x128 tile, BK=8, 256 threads, 8x8 per thread via 8x4 packed accumulators
__global__ void __launch_bounds__(256)
k_gemm(const float* __restrict__ A, const float* __restrict__ B,
       const float* __restrict__ bias, float* __restrict__ C,
       int M, int do_relu) {
    const int BM = 128, BN = 128, BK = 8, K = HID, N = HID;
    __shared__ float2 As[BK][BM];   // duplicated {a,a} pairs
    __shared__ float  Bs[BK][BN];

    int tid = threadIdx.x;
    int rowBase = blockIdx.y * BM;
    int colBase = blockIdx.x * BN;

    int arow = tid >> 1, acol = (tid & 1) * 4;    // A tile: 128 rows x 8 cols
    int brow = tid >> 5, bcol = (tid & 31) * 4;   // B tile: 8 rows x 128 cols
    int tr = tid >> 4, tc = tid & 15;             // 16x16 threads, 8x8 each

    unsigned long long acc2[8][4];
#pragma unroll
    for (int i = 0; i < 8; i++)
#pragma unroll
        for (int j = 0; j < 4; j++) acc2[i][j] = 0ull;

    for (int kt = 0; kt < K; kt += BK) {
        float4 av = make_float4(0.f, 0.f, 0.f, 0.f);
        int garow = rowBase + arow;
        if (garow < M)
            av = *(const float4*)(A + (size_t)garow * K + kt + acol);
        As[acol + 0][arow] = make_float2(av.x, av.x);
        As[acol + 1][arow] = make_float2(av.y, av.y);
        As[acol + 2][arow] = make_float2(av.z, av.z);
        As[acol + 3][arow] = make_float2(av.w, av.w);

        float4 bv = *(const float4*)(B + (size_t)(kt + brow) * N + colBase + bcol);
        *(float4*)&Bs[brow][bcol] = bv;
        __syncthreads();

#pragma unroll
        for (int k = 0; k < BK; k++) {
            unsigned long long a2[8], b2[4];
            const unsigned long long* pa =
                (const unsigned long long*)&As[k][tr * 8];
            const unsigned long long* pb =
                (const unsigned long long*)&Bs[k][tc * 8];
#pragma unroll
            for (int i = 0; i < 8; i++) a2[i] = pa[i];
#pragma unroll
            for (int j = 0; j < 4; j++) b2[j] = pb[j];
#pragma unroll
            for (int i = 0; i < 8; i++)
#pragma unroll
                for (int j = 0; j < 4; j++) fma2(acc2[i][j], a2[i], b2[j]);
        }
        __syncthreads();
    }

    float rbias[8];
#pragma unroll
    for (int j = 0; j < 8; j++) rbias[j] = bias[colBase + tc * 8 + j];

#pragma unroll
    for (int i = 0; i < 8; i++) {
        int row = rowBase + tr * 8 + i;
        if (row >= M) continue;
        float* cptr = C + (size_t)row * N + colBase + tc * 8;
        float vals[8];
#pragma unroll
        for (int j = 0; j < 4; j++) {
            unsigned long long v = acc2[i][j];
            vals[2 * j + 0] = __uint_as_float((unsigned)(v & 0xffffffffull));
            vals[2 * j + 1] = __uint_as_float((unsigned)(v >> 32));
        }
#pragma unroll
        for (int j4 = 0; j4 < 2; j4++) {
            float4 v;
            v.x = vals[j4 * 4 + 0] + rbias[j4 * 4 + 0];
            v.y = vals[j4 * 4 + 1] + rbias[j4 * 4 + 1];
            v.z = vals[j4 * 4 + 2] + rbias[j4 * 4 + 2];
            v.w = vals[j4 * 4 + 3] + rbias[j4 * 4 + 3];
            if (do_relu) {
                v.x = fmaxf(v.x, 0.f); v.y = fmaxf(v.y, 0.f);
                v.z = fmaxf(v.z, 0.f); v.w = fmaxf(v.w, 0.f);
            }
            *(float4*)(cptr + j4 * 4) = v;
        }
    }
}

// ---------------- threefry2x32 (JAX-exact) ----------------------------------
__device__ __forceinline__ uint32_t tf_rotl(uint32_t v, int s) {
    return (v << s) | (v >> (32 - s));
}

__device__ __forceinline__ uint2 threefry2x32(uint32_t k0, uint32_t k1,
                                              uint32_t x0, uint32_t x1) {
    uint32_t ks2 = k0 ^ k1 ^ 0x1BD11BDAu;
    x0 += k0; x1 += k1;
#define TF_R(r) { x0 += x1; x1 = tf_rotl(x1, r); x1 ^= x0; }
    TF_R(13) TF_R(15) TF_R(26) TF_R(6)   x0 += k1;  x1 += ks2 + 1u;
    TF_R(17) TF_R(29) TF_R(16) TF_R(24)  x0 += ks2; x1 += k0 + 2u;
    TF_R(13) TF_R(15) TF_R(26) TF_R(6)   x0 += k0;  x1 += k1 + 3u;
    TF_R(17) TF_R(29) TF_R(16) TF_R(24)  x0 += k1;  x1 += ks2 + 4u;
    TF_R(13) TF_R(15) TF_R(26) TF_R(6)   x0 += ks2; x1 += k0 + 5u;
#undef TF_R
    return make_uint2(x0, x1);
}

__device__ __forceinline__ float bits_to_eps(uint32_t bits) {
    float u01 = __uint_as_float((bits >> 9) | 0x3f800000u) - 1.0f;
    const float lo = __uint_as_float(0xBF7FFFFFu);   // nextafter(-1f, 0f)
    const float span = 1.0f - lo;
    float v = __fadd_rn(__fmul_rn(u01, span), lo);
    v = fmaxf(lo, v);
    return 1.41421356f * erfinvf(v);
}

// ---------------- z = mu + exp(logstd) * eps ---------------------------------
__global__ void k_z(const float* __restrict__ mu, const float* __restrict__ ls,
                    float* __restrict__ z, int total) {
    int i = blockIdx.x * blockDim.x + threadIdx.x;
    if (i >= total) return;
    uint2 r = threefry2x32(0u, 1u, 0u, (uint32_t)i);
    uint32_t bits = r.x ^ r.y;                        // partitionable XOR fold
    float eps = bits_to_eps(bits);
    z[i] = mu[i] + expf(ls[i]) * eps;
}

// ---------------- launch ------------------------------------------------------
extern "C" void kernel_launch(void* const* d_in, const int* in_sizes, int n_in,
                              void* d_out, int out_size) {
    const float* x   = (const float*)d_in[0];
    const int*   ei  = (const int*)d_in[1];
    const float* W1  = (const float*)d_in[2];
    const float* b1  = (const float*)d_in[3];
    const float* Wmu = (const float*)d_in[4];
    const float* bmu = (const float*)d_in[5];
    const float* Wls = (const float*)d_in[6];
    const float* bls = (const float*)d_in[7];
    int E = in_sizes[1] / 2;

    float* out = (float*)d_out;
    float* z   = out;
    float* mu  = out + (size_t)NH;
    float* ls  = out + 2 * (size_t)NH;

    float* buf1; float* buf2;
    cudaGetSymbolAddress((void**)&buf1, g_buf1);
    cudaGetSymbolAddress((void**)&buf2, g_buf2);

    // graph prep: degrees, dinv, CSR
    k_zero_deg<<<(N_NODES + 255) / 256, 256>>>();
    k_count_deg<<<(E + 255) / 256, 256>>>(ei, E);
    k_dinv<<<(N_NODES + 255) / 256, 256>>>();
    k_scan<<<1, 1024>>>(E);
    k_fill<<<(E + 255) / 256, 256>>>(ei, E);

    dim3 gspmm((N_NODES + 7) / 8);
    dim3 g1(HID / 128, (N_NODES + 127) / 128);

    // t = A_norm @ x -> buf1
    k_spmm_csr<<<gspmm, 256>>>(x, buf1);
    // h = relu(t @ W1 + b1) -> buf2
    k_gemm<<<g1, 256>>>(buf1, W1, b1, buf2, N_NODES, 1);
    // p = A_norm @ h -> buf1
    k_spmm_csr<<<gspmm, 256>>>(buf2, buf1);
    // mu / logstd
    k_gemm<<<g1, 256>>>(buf1, Wmu, bmu, mu, N_NODES, 0);
    k_gemm<<<g1, 256>>>(buf1, Wls, bls, ls, N_NODES, 0);
    // z
    k_z<<<(NH + 255) / 256, 256>>>(mu, ls, z, NH);
}

// round 6
// speedup vs baseline: 1.3129x; 1.0542x over previous
#include <cuda_runtime.h>
#include <cstdint>

#define N_NODES 50000
#define HID     256
#define NH      (N_NODES * HID)
#define MAX_E   2000000
#define NB_SCAN 49                      // ceil(50000/1024)

// ---------------- scratch (static device globals; no allocation) ------------
__device__ float g_buf1[NH];            // t = A@x, later p = A@h
__device__ float g_buf2[NH];            // h
__device__ float g_dinv[N_NODES];
__device__ int   g_deg[N_NODES];
__device__ int   g_rowptr[N_NODES + 1];
__device__ int   g_cur[N_NODES];
__device__ int   g_col[MAX_E];
__device__ int   g_bsum[NB_SCAN];

// ---------------- degree count ----------------------------------------------
__global__ void k_count_deg(const int* __restrict__ ei, int E) {
    int i = blockIdx.x * blockDim.x + threadIdx.x;
    if (i < E) atomicAdd(&g_deg[ei[E + i]], 1);
}

// ---------------- scan phase 1: per-block exclusive scan + dinv --------------
__global__ void __launch_bounds__(1024) k_scan1() {
    __shared__ int sh[1024];
    int tid = threadIdx.x;
    int i = blockIdx.x * 1024 + tid;
    int v = (i < N_NODES) ? g_deg[i] : 0;
    if (i < N_NODES) g_dinv[i] = rsqrtf((float)(v + 1));   // +1 self loop
    sh[tid] = v;
    __syncthreads();
#pragma unroll
    for (int off = 1; off < 1024; off <<= 1) {
        int t = (tid >= off) ? sh[tid - off] : 0;
        __syncthreads();
        sh[tid] += t;
        __syncthreads();
    }
    if (i < N_NODES) g_rowptr[i] = sh[tid] - v;            // local exclusive
    if (tid == 1023) g_bsum[blockIdx.x] = sh[1023];
}

// ---------------- scan phase 2: add block prefixes ---------------------------
__global__ void __launch_bounds__(1024) k_scan2(int E) {
    __shared__ int pf[NB_SCAN];
    int tid = threadIdx.x;
    if (tid == 0) {                     // tiny serial scan of 49 partials
        int run = 0;
#pragma unroll
        for (int b = 0; b < NB_SCAN; b++) { pf[b] = run; run += g_bsum[b]; }
    }
    __syncthreads();
    int i = blockIdx.x * 1024 + tid;
    if (i < N_NODES) {
        int r = g_rowptr[i] + pf[blockIdx.x];
        g_rowptr[i] = r;
        g_cur[i] = r;
    }
    if (blockIdx.x == 0 && tid == 0) g_rowptr[N_NODES] = E;
}

__global__ void k_fill(const int* __restrict__ ei, int E) {
    int e = blockIdx.x * blockDim.x + threadIdx.x;
    if (e < E) {
        int d = ei[E + e];
        int pos = atomicAdd(&g_cur[d], 1);
        g_col[pos] = ei[e];
    }
}

// ---------------- CSR SpMM: Y[d] = dd * sum_s dinv[s]*X[s] + dd^2 * X[d] ----
__global__ void __launch_bounds__(256) k_spmm_csr(const float* __restrict__ X,
                                                  float* __restrict__ Y) {
    int node = blockIdx.x * 8 + (threadIdx.x >> 5);
    int lane = threadIdx.x & 31;
    if (node >= N_NODES) return;
    const float4* X4 = (const float4*)X;
    float4* Y4 = (float4*)Y;

    float4 s0 = make_float4(0.f, 0.f, 0.f, 0.f);
    float4 s1 = make_float4(0.f, 0.f, 0.f, 0.f);
    int beg = g_rowptr[node];
    int end = g_rowptr[node + 1];

    int e = beg;
    for (; e + 2 <= end; e += 2) {
        int sa = __ldg(&g_col[e]);
        int sb = __ldg(&g_col[e + 1]);
        float wa = g_dinv[sa];
        float wb = g_dinv[sb];
        const float4* pa = X4 + (size_t)sa * 64;
        const float4* pb = X4 + (size_t)sb * 64;
        float4 a0 = __ldg(pa + lane), a1 = __ldg(pa + lane + 32);
        float4 b0 = __ldg(pb + lane), b1 = __ldg(pb + lane + 32);
        s0.x += wa * a0.x + wb * b0.x; s0.y += wa * a0.y + wb * b0.y;
        s0.z += wa * a0.z + wb * b0.z; s0.w += wa * a0.w + wb * b0.w;
        s1.x += wa * a1.x + wb * b1.x; s1.y += wa * a1.y + wb * b1.y;
        s1.z += wa * a1.z + wb * b1.z; s1.w += wa * a1.w + wb * b1.w;
    }
    if (e < end) {
        int sa = __ldg(&g_col[e]);
        float wa = g_dinv[sa];
        const float4* pa = X4 + (size_t)sa * 64;
        float4 a0 = __ldg(pa + lane), a1 = __ldg(pa + lane + 32);
        s0.x += wa * a0.x; s0.y += wa * a0.y; s0.z += wa * a0.z; s0.w += wa * a0.w;
        s1.x += wa * a1.x; s1.y += wa * a1.y; s1.z += wa * a1.z; s1.w += wa * a1.w;
    }

    float dd = g_dinv[node];
    float dd2 = dd * dd;
    const float4* px = X4 + (size_t)node * 64;
    float4 x0 = __ldg(px + lane), x1 = __ldg(px + lane + 32);
    float4 o0, o1;
    o0.x = dd * s0.x + dd2 * x0.x; o0.y = dd * s0.y + dd2 * x0.y;
    o0.z = dd * s0.z + dd2 * x0.z; o0.w = dd * s0.w + dd2 * x0.w;
    o1.x = dd * s1.x + dd2 * x1.x; o1.y = dd * s1.y + dd2 * x1.y;
    o1.z = dd * s1.z + dd2 * x1.z; o1.w = dd * s1.w + dd2 * x1.w;
    Y4[(size_t)node * 64 + lane] = o0;
    Y4[(size_t)node * 64 + lane + 32] = o1;
}

// ---------------- packed f32x2 FMA helper -----------------------------------
__device__ __forceinline__ void fma2(unsigned long long& acc,
                                     unsigned long long a,
                                     unsigned long long b) {
    asm("fma.rn.f32x2 %0, %1, %2, %0;" : "+l"(acc) : "l"(a), "l"(b));
}

// ---------------- threefry2x32 (JAX-exact) ----------------------------------
__device__ __forceinline__ uint32_t tf_rotl(uint32_t v, int s) {
    return (v << s) | (v >> (32 - s));
}

__device__ __forceinline__ uint2 threefry2x32(uint32_t k0, uint32_t k1,
                                              uint32_t x0, uint32_t x1) {
    uint32_t ks2 = k0 ^ k1 ^ 0x1BD11BDAu;
    x0 += k0; x1 += k1;
#define TF_R(r) { x0 += x1; x1 = tf_rotl(x1, r); x1 ^= x0; }
    TF_R(13) TF_R(15) TF_R(26) TF_R(6)   x0 += k1;  x1 += ks2 + 1u;
    TF_R(17) TF_R(29) TF_R(16) TF_R(24)  x0 += ks2; x1 += k0 + 2u;
    TF_R(13) TF_R(15) TF_R(26) TF_R(6)   x0 += k0;  x1 += k1 + 3u;
    TF_R(17) TF_R(29) TF_R(16) TF_R(24)  x0 += k1;  x1 += ks2 + 4u;
    TF_R(13) TF_R(15) TF_R(26) TF_R(6)   x0 += ks2; x1 += k0 + 5u;
#undef TF_R
    return make_uint2(x0, x1);
}

__device__ __forceinline__ float bits_to_eps(uint32_t bits) {
    float u01 = __uint_as_float((bits >> 9) | 0x3f800000u) - 1.0f;
    const float lo = __uint_as_float(0xBF7FFFFFu);   // nextafter(-1f, 0f)
    const float span = 1.0f - lo;
    float v = __fadd_rn(__fmul_rn(u01, span), lo);
    v = fmaxf(lo, v);
    return 1.41421356f * erfinvf(v);
}

// ---------------- SGEMM (f32x2): C = act(A[M,256] @ B[256,256] + bias) ------
// mode 0: plain   mode 1: relu   mode 2: write ls to C AND z = mu + exp(ls)*eps
__global__ void __launch_bounds__(256)
k_gemm(const float* __restrict__ A, const float* __restrict__ B,
       const float* __restrict__ bias, float* __restrict__ C,
       int M, int mode, const float* __restrict__ muIn, float* __restrict__ zOut) {
    const int BM = 128, BN = 128, BK = 8, K = HID, N = HID;
    __shared__ float2 As[BK][BM];   // duplicated {a,a} pairs
    __shared__ float  Bs[BK][BN];

    int tid = threadIdx.x;
    int rowBase = blockIdx.y * BM;
    int colBase = blockIdx.x * BN;

    int arow = tid >> 1, acol = (tid & 1) * 4;
    int brow = tid >> 5, bcol = (tid & 31) * 4;
    int tr = tid >> 4, tc = tid & 15;

    unsigned long long acc2[8][4];
#pragma unroll
    for (int i = 0; i < 8; i++)
#pragma unroll
        for (int j = 0; j < 4; j++) acc2[i][j] = 0ull;

    for (int kt = 0; kt < K; kt += BK) {
        float4 av = make_float4(0.f, 0.f, 0.f, 0.f);
        int garow = rowBase + arow;
        if (garow < M)
            av = *(const float4*)(A + (size_t)garow * K + kt + acol);
        As[acol + 0][arow] = make_float2(av.x, av.x);
        As[acol + 1][arow] = make_float2(av.y, av.y);
        As[acol + 2][arow] = make_float2(av.z, av.z);
        As[acol + 3][arow] = make_float2(av.w, av.w);

        float4 bv = *(const float4*)(B + (size_t)(kt + brow) * N + colBase + bcol);
        *(float4*)&Bs[brow][bcol] = bv;
        __syncthreads();

#pragma unroll
        for (int k = 0; k < BK; k++) {
            unsigned long long a2[8], b2[4];
            const unsigned long long* pa =
                (const unsigned long long*)&As[k][tr * 8];
            const unsigned long long* pb =
                (const unsigned long long*)&Bs[k][tc * 8];
#pragma unroll
            for (int i = 0; i < 8; i++) a2[i] = pa[i];
#pragma unroll
            for (int j = 0; j < 4; j++) b2[j] = pb[j];
#pragma unroll
            for (int i = 0; i < 8; i++)
#pragma unroll
                for (int j = 0; j < 4; j++) fma2(acc2[i][j], a2[i], b2[j]);
        }
        __syncthreads();
    }

    float rbias[8];
#pragma unroll
    for (int j = 0; j < 8; j++) rbias[j] = bias[colBase + tc * 8 + j];

#pragma unroll
    for (int i = 0; i < 8; i++) {
        int row = rowBase + tr * 8 + i;
        if (row >= M) continue;
        size_t base = (size_t)row * N + colBase + tc * 8;
        float vals[8];
#pragma unroll
        for (int j = 0; j < 4; j++) {
            unsigned long long v = acc2[i][j];
            vals[2 * j + 0] = __uint_as_float((unsigned)(v & 0xffffffffull));
            vals[2 * j + 1] = __uint_as_float((unsigned)(v >> 32));
        }
#pragma unroll
        for (int j4 = 0; j4 < 2; j4++) {
            float4 v;
            v.x = vals[j4 * 4 + 0] + rbias[j4 * 4 + 0];
            v.y = vals[j4 * 4 + 1] + rbias[j4 * 4 + 1];
            v.z = vals[j4 * 4 + 2] + rbias[j4 * 4 + 2];
            v.w = vals[j4 * 4 + 3] + rbias[j4 * 4 + 3];
            if (mode == 1) {
                v.x = fmaxf(v.x, 0.f); v.y = fmaxf(v.y, 0.f);
                v.z = fmaxf(v.z, 0.f); v.w = fmaxf(v.w, 0.f);
            }
            *(float4*)(C + base + j4 * 4) = v;     // ls (or h / mu)
            if (mode == 2) {
                // z = mu + exp(ls) * eps, threefry index = linear elem index
                unsigned idx0 = (unsigned)(base + j4 * 4);
                float4 m = *(const float4*)(muIn + base + j4 * 4);
                float4 zv;
                uint2 r0 = threefry2x32(0u, 1u, 0u, idx0 + 0);
                uint2 r1 = threefry2x32(0u, 1u, 0u, idx0 + 1);
                uint2 r2 = threefry2x32(0u, 1u, 0u, idx0 + 2);
                uint2 r3 = threefry2x32(0u, 1u, 0u, idx0 + 3);
                zv.x = m.x + expf(v.x) * bits_to_eps(r0.x ^ r0.y);
                zv.y = m.y + expf(v.y) * bits_to_eps(r1.x ^ r1.y);
                zv.z = m.z + expf(v.z) * bits_to_eps(r2.x ^ r2.y);
                zv.w = m.w + expf(v.w) * bits_to_eps(r3.x ^ r3.y);
                *(float4*)(zOut + base + j4 * 4) = zv;
            }
        }
    }
}

// ---------------- launch ------------------------------------------------------
extern "C" void kernel_launch(void* const* d_in, const int* in_sizes, int n_in,
                              void* d_out, int out_size) {
    const float* x   = (const float*)d_in[0];
    const int*   ei  = (const int*)d_in[1];
    const float* W1  = (const float*)d_in[2];
    const float* b1  = (const float*)d_in[3];
    const float* Wmu = (const float*)d_in[4];
    const float* bmu = (const float*)d_in[5];
    const float* Wls = (const float*)d_in[6];
    const float* bls = (const float*)d_in[7];
    int E = in_sizes[1] / 2;

    float* out = (float*)d_out;
    float* z   = out;
    float* mu  = out + (size_t)NH;
    float* ls  = out + 2 * (size_t)NH;

    float* buf1; float* buf2; int* degp;
    cudaGetSymbolAddress((void**)&buf1, g_buf1);
    cudaGetSymbolAddress((void**)&buf2, g_buf2);
    cudaGetSymbolAddress((void**)&degp, g_deg);

    // graph prep: degrees, dinv, CSR
    cudaMemsetAsync(degp, 0, N_NODES * sizeof(int));
    k_count_deg<<<(E + 255) / 256, 256>>>(ei, E);
    k_scan1<<<NB_SCAN, 1024>>>();
    k_scan2<<<NB_SCAN, 1024>>>(E);
    k_fill<<<(E + 255) / 256, 256>>>(ei, E);

    dim3 gspmm((N_NODES + 7) / 8);
    dim3 g1(HID / 128, (N_NODES + 127) / 128);

    // t = A_norm @ x -> buf1
    k_spmm_csr<<<gspmm, 256>>>(x, buf1);
    // h = relu(t @ W1 + b1) -> buf2
    k_gemm<<<g1, 256>>>(buf1, W1, b1, buf2, N_NODES, 1, nullptr, nullptr);
    // p = A_norm @ h -> buf1
    k_spmm_csr<<<gspmm, 256>>>(buf2, buf1);
    // mu
    k_gemm<<<g1, 256>>>(buf1, Wmu, bmu, mu, N_NODES, 0, nullptr, nullptr);
    // ls + fused z
    k_gemm<<<g1, 256>>>(buf1, Wls, bls, ls, N_NODES, 2, mu, z);
}

// round 8
// speedup vs baseline: 1.8312x; 1.3948x over previous
#include <cuda_runtime.h>
#include <cuda_bf16.h>
#include <cstdint>

#define N_NODES 50000
#define HID     256
#define NH      (N_NODES * HID)
#define MAX_E   2000000
#define NB_SCAN 49                      // ceil(50000/1024)
#define NBLK_M  782                     // ceil(50000/64)

// ---------------- scratch (static device globals; no allocation) ------------
__device__ float g_buf1[NH];            // t = A@x, later p = A@h
__device__ float g_buf2[NH];            // h
__device__ float g_dinv[N_NODES];
__device__ int   g_deg[N_NODES];
__device__ int   g_rowptr[N_NODES + 1];
__device__ int   g_cur[N_NODES];
__device__ int   g_col[MAX_E];
__device__ int   g_bsum[NB_SCAN];
// weight images: per weight 128 kpairs x 256 cols, uint32 = 2 packed bf16 (k, k+1)
// column index pre-swizzled with n ^ ((kp&3)<<3)
__device__ uint32_t g_Bh[3 * 32768];
__device__ uint32_t g_Bl[3 * 32768];

// ---------------- degree count ----------------------------------------------
__global__ void k_count_deg(const int* __restrict__ ei, int E) {
    int i = blockIdx.x * blockDim.x + threadIdx.x;
    if (i < E) atomicAdd(&g_deg[ei[E + i]], 1);
}

// ---------------- scan phase 1 ------------------------------------------------
__global__ void __launch_bounds__(1024) k_scan1() {
    __shared__ int sh[1024];
    int tid = threadIdx.x;
    int i = blockIdx.x * 1024 + tid;
    int v = (i < N_NODES) ? g_deg[i] : 0;
    if (i < N_NODES) g_dinv[i] = rsqrtf((float)(v + 1));   // +1 self loop
    sh[tid] = v;
    __syncthreads();
#pragma unroll
    for (int off = 1; off < 1024; off <<= 1) {
        int t = (tid >= off) ? sh[tid - off] : 0;
        __syncthreads();
        sh[tid] += t;
        __syncthreads();
    }
    if (i < N_NODES) g_rowptr[i] = sh[tid] - v;
    if (tid == 1023) g_bsum[blockIdx.x] = sh[1023];
}

// ---------------- scan phase 2 ------------------------------------------------
__global__ void __launch_bounds__(1024) k_scan2(int E) {
    __shared__ int pf[NB_SCAN];
    int tid = threadIdx.x;
    if (tid == 0) {
        int run = 0;
#pragma unroll
        for (int b = 0; b < NB_SCAN; b++) { pf[b] = run; run += g_bsum[b]; }
    }
    __syncthreads();
    int i = blockIdx.x * 1024 + tid;
    if (i < N_NODES) {
        int r = g_rowptr[i] + pf[blockIdx.x];
        g_rowptr[i] = r;
        g_cur[i] = r;
    }
    if (blockIdx.x == 0 && tid == 0) g_rowptr[N_NODES] = E;
}

__global__ void k_fill(const int* __restrict__ ei, int E) {
    int e = blockIdx.x * blockDim.x + threadIdx.x;
    if (e < E) {
        int d = ei[E + e];
        int pos = atomicAdd(&g_cur[d], 1);
        g_col[pos] = ei[e];
    }
}

// ---------------- bf16 pack helpers ------------------------------------------
__device__ __forceinline__ uint32_t pack2bf16(float a, float b) {
    return (uint32_t)__bfloat16_as_ushort(__float2bfloat16(a))
         | ((uint32_t)__bfloat16_as_ushort(__float2bfloat16(b)) << 16);
}

// ---------------- weight conversion: f32 [K][N] -> packed split-bf16 images ---
__global__ void k_convW(const float* __restrict__ W1,
                        const float* __restrict__ Wmu,
                        const float* __restrict__ Wls) {
    int idx = blockIdx.x * 256 + threadIdx.x;   // 3 * 32768 threads
    int w = idx >> 15;
    int e = idx & 32767;                        // kp*256 + n
    int kp = e >> 8, n = e & 255;
    const float* W = (w == 0) ? W1 : (w == 1) ? Wmu : Wls;
    float v0 = W[(2 * kp) * 256 + n];
    float v1 = W[(2 * kp + 1) * 256 + n];
    __nv_bfloat16 h0 = __float2bfloat16(v0);
    __nv_bfloat16 h1 = __float2bfloat16(v1);
    float l0 = v0 - __bfloat162float(h0);
    float l1 = v1 - __bfloat162float(h1);
    int ns = n ^ ((kp & 3) << 3);
    g_Bh[w * 32768 + kp * 256 + ns] =
        (uint32_t)__bfloat16_as_ushort(h0) | ((uint32_t)__bfloat16_as_ushort(h1) << 16);
    g_Bl[w * 32768 + kp * 256 + ns] = pack2bf16(l0, l1);
}

// ---------------- CSR SpMM: Y[d] = dd * sum_s dinv[s]*X[s] + dd^2 * X[d] ----
__global__ void __launch_bounds__(256) k_spmm_csr(const float* __restrict__ X,
                                                  float* __restrict__ Y) {
    int node = blockIdx.x * 8 + (threadIdx.x >> 5);
    int lane = threadIdx.x & 31;
    if (node >= N_NODES) return;
    const float4* X4 = (const float4*)X;
    float4* Y4 = (float4*)Y;

    float4 s0 = make_float4(0.f, 0.f, 0.f, 0.f);
    float4 s1 = make_float4(0.f, 0.f, 0.f, 0.f);
    int beg = g_rowptr[node];
    int end = g_rowptr[node + 1];

    int e = beg;
    for (; e + 2 <= end; e += 2) {
        int sa = __ldg(&g_col[e]);
        int sb = __ldg(&g_col[e + 1]);
        float wa = g_dinv[sa];
        float wb = g_dinv[sb];
        const float4* pa = X4 + (size_t)sa * 64;
        const float4* pb = X4 + (size_t)sb * 64;
        float4 a0 = __ldg(pa + lane), a1 = __ldg(pa + lane + 32);
        float4 b0 = __ldg(pb + lane), b1 = __ldg(pb + lane + 32);
        s0.x += wa * a0.x + wb * b0.x; s0.y += wa * a0.y + wb * b0.y;
        s0.z += wa * a0.z + wb * b0.z; s0.w += wa * a0.w + wb * b0.w;
        s1.x += wa * a1.x + wb * b1.x; s1.y += wa * a1.y + wb * b1.y;
        s1.z += wa * a1.z + wb * b1.z; s1.w += wa * a1.w + wb * b1.w;
    }
    if (e < end) {
        int sa = __ldg(&g_col[e]);
        float wa = g_dinv[sa];
        const float4* pa = X4 + (size_t)sa * 64;
        float4 a0 = __ldg(pa + lane), a1 = __ldg(pa + lane + 32);
        s0.x += wa * a0.x; s0.y += wa * a0.y; s0.z += wa * a0.z; s0.w += wa * a0.w;
        s1.x += wa * a1.x; s1.y += wa * a1.y; s1.z += wa * a1.z; s1.w += wa * a1.w;
    }

    float dd = g_dinv[node];
    float dd2 = dd * dd;
    const float4* px = X4 + (size_t)node * 64;
    float4 x0 = __ldg(px + lane), x1 = __ldg(px + lane + 32);
    float4 o0, o1;
    o0.x = dd * s0.x + dd2 * x0.x; o0.y = dd * s0.y + dd2 * x0.y;
    o0.z = dd * s0.z + dd2 * x0.z; o0.w = dd * s0.w + dd2 * x0.w;
    o1.x = dd * s1.x + dd2 * x1.x; o1.y = dd * s1.y + dd2 * x1.y;
    o1.z = dd * s1.z + dd2 * x1.z; o1.w = dd * s1.w + dd2 * x1.w;
    Y4[(size_t)node * 64 + lane] = o0;
    Y4[(size_t)node * 64 + lane + 32] = o1;
}

// ---------------- threefry2x32 (JAX-exact) ----------------------------------
__device__ __forceinline__ uint32_t tf_rotl(uint32_t v, int s) {
    return (v << s) | (v >> (32 - s));
}

__device__ __forceinline__ uint2 threefry2x32(uint32_t k0, uint32_t k1,
                                              uint32_t x0, uint32_t x1) {
    uint32_t ks2 = k0 ^ k1 ^ 0x1BD11BDAu;
    x0 += k0; x1 += k1;
#define TF_R(r) { x0 += x1; x1 = tf_rotl(x1, r); x1 ^= x0; }
    TF_R(13) TF_R(15) TF_R(26) TF_R(6)   x0 += k1;  x1 += ks2 + 1u;
    TF_R(17) TF_R(29) TF_R(16) TF_R(24)  x0 += ks2; x1 += k0 + 2u;
    TF_R(13) TF_R(15) TF_R(26) TF_R(6)   x0 += k0;  x1 += k1 + 3u;
    TF_R(17) TF_R(29) TF_R(16) TF_R(24)  x0 += k1;  x1 += ks2 + 4u;
    TF_R(13) TF_R(15) TF_R(26) TF_R(6)   x0 += ks2; x1 += k0 + 5u;
#undef TF_R
    return make_uint2(x0, x1);
}

__device__ __forceinline__ float bits_to_eps(uint32_t bits) {
    float u01 = __uint_as_float((bits >> 9) | 0x3f800000u) - 1.0f;
    const float lo = __uint_as_float(0xBF7FFFFFu);
    const float span = 1.0f - lo;
    float v = __fadd_rn(__fmul_rn(u01, span), lo);
    v = fmaxf(lo, v);
    return 1.41421356f * erfinvf(v);
}

// ---------------- mma.sync m16n8k16 bf16 wrapper ------------------------------
__device__ __forceinline__ void mma16816(float* d, const uint32_t* a,
                                         uint32_t b0, uint32_t b1) {
    asm volatile(
        "mma.sync.aligned.m16n8k16.row.col.f32.bf16.bf16.f32 "
        "{%0,%1,%2,%3}, {%4,%5,%6,%7}, {%8,%9}, {%0,%1,%2,%3};"
        : "+f"(d[0]), "+f"(d[1]), "+f"(d[2]), "+f"(d[3])
        : "r"(a[0]), "r"(a[1]), "r"(a[2]), "r"(a[3]), "r"(b0), "r"(b1));
}

// ---------------- tensor-core GEMM via mma.sync -------------------------------
// C[M,256] = act(A[M,256] @ W + bias).  Split-bf16 3-term emulation.
// CTA: 64 rows x 256 cols, 256 threads (8 warps as 2m x 4n), warp tile 32x64.
// mode 0: plain (mu)   mode 1: relu (h)   mode 2: ls + fused z (reads muIn)
// SMEM: bias @0 (1KB), Apack_h @1024 (8KB), Apack_l @9216 (8KB),
//       Bh @17408 (32KB), Bl @50176 (32KB)  -> total 82944 B
#define SMEM_MMA 82944

__global__ void __launch_bounds__(256)
k_gemm_mma(const float* __restrict__ A, int M,
           const uint32_t* __restrict__ Bh, const uint32_t* __restrict__ Bl,
           const float* __restrict__ bias, float* __restrict__ C,
           int mode, const float* __restrict__ muIn, float* __restrict__ zOut) {
    extern __shared__ char smem[];
    float*    sBias = (float*)smem;
    uint32_t* sAh = (uint32_t*)(smem + 1024);
    uint32_t* sAl = (uint32_t*)(smem + 9216);
    uint32_t* sBh = (uint32_t*)(smem + 17408);
    uint32_t* sBl = (uint32_t*)(smem + 50176);

    int tid = threadIdx.x;
    int l = tid & 31;
    int w = tid >> 5;
    int wm = w >> 2;          // 0..1  (rows wm*32)
    int wn = w & 3;           // 0..3  (cols wn*64)
    int rowBase = blockIdx.x * 64;

    sBias[tid] = bias[tid];   // 256 threads, 256 cols

    float acc[2][8][4];
#pragma unroll
    for (int mt = 0; mt < 2; mt++)
#pragma unroll
        for (int nt = 0; nt < 8; nt++)
#pragma unroll
            for (int r = 0; r < 4; r++) acc[mt][nt][r] = 0.f;

    int arow = tid & 63;          // conversion role
    int kseg = tid >> 6;          // 0..3 -> kpairs kseg*8..+7
    int grow = rowBase + arow;

    for (int c = 0; c < 4; c++) {
        __syncthreads();          // previous chunk fully consumed
        // --- A chunk [64 x 64] f32 -> split bf16 packed, swizzled
        {
            float4 f[4];
            if (grow < M) {
                const float4* p =
                    (const float4*)(A + (size_t)grow * 256 + c * 64 + kseg * 16);
                f[0] = __ldg(p); f[1] = __ldg(p + 1);
                f[2] = __ldg(p + 2); f[3] = __ldg(p + 3);
            } else {
                f[0] = f[1] = f[2] = f[3] = make_float4(0.f, 0.f, 0.f, 0.f);
            }
            const float* fv = (const float*)f;
#pragma unroll
            for (int i = 0; i < 8; i++) {
                int kp = kseg * 8 + i;
                float v0 = fv[2 * i], v1 = fv[2 * i + 1];
                __nv_bfloat16 h0 = __float2bfloat16(v0);
                __nv_bfloat16 h1 = __float2bfloat16(v1);
                uint32_t hp = (uint32_t)__bfloat16_as_ushort(h0)
                            | ((uint32_t)__bfloat16_as_ushort(h1) << 16);
                uint32_t lp = pack2bf16(v0 - __bfloat162float(h0),
                                        v1 - __bfloat162float(h1));
                int sr = arow ^ ((kp & 3) << 3);
                sAh[kp * 64 + sr] = hp;
                sAl[kp * 64 + sr] = lp;
            }
        }
        // --- B chunk: copy 32KB hi + 32KB lo (pre-swizzled images)
        {
            const uint4* gh = (const uint4*)(Bh + c * 8192);
            const uint4* gl = (const uint4*)(Bl + c * 8192);
            uint4* dh = (uint4*)sBh;
            uint4* dl = (uint4*)sBl;
#pragma unroll
            for (int i = 0; i < 8; i++) {
                dh[tid + i * 256] = __ldg(gh + tid + i * 256);
                dl[tid + i * 256] = __ldg(gl + tid + i * 256);
            }
        }
        __syncthreads();

        // --- mma over 4 k-steps of 16
#pragma unroll
        for (int ks = 0; ks < 4; ks++) {
            int kp0 = ks * 8 + (l & 3);
            int sw = (l & 3) << 3;                 // (kp0&3)<<3 == (l&3)<<3
            uint32_t ah[2][4], al2[2][4];
#pragma unroll
            for (int mt = 0; mt < 2; mt++) {
                int r0 = wm * 32 + mt * 16 + (l >> 2);
                int i00 = kp0 * 64 + (r0 ^ sw);
                int i01 = kp0 * 64 + ((r0 + 8) ^ sw);
                int i10 = (kp0 + 4) * 64 + (r0 ^ sw);
                int i11 = (kp0 + 4) * 64 + ((r0 + 8) ^ sw);
                ah[mt][0] = sAh[i00]; ah[mt][1] = sAh[i01];
                ah[mt][2] = sAh[i10]; ah[mt][3] = sAh[i11];
                al2[mt][0] = sAl[i00]; al2[mt][1] = sAl[i01];
                al2[mt][2] = sAl[i10]; al2[mt][3] = sAl[i11];
            }
#pragma unroll
            for (int nt = 0; nt < 8; nt++) {
                int nc = wn * 64 + nt * 8 + (l >> 2);
                int nsw = nc ^ sw;
                uint32_t bh0 = sBh[kp0 * 256 + nsw];
                uint32_t bh1 = sBh[(kp0 + 4) * 256 + nsw];
                uint32_t bl0 = sBl[kp0 * 256 + nsw];
                uint32_t bl1 = sBl[(kp0 + 4) * 256 + nsw];
#pragma unroll
                for (int mt = 0; mt < 2; mt++) {
                    mma16816(acc[mt][nt], ah[mt], bh0, bh1);
                    mma16816(acc[mt][nt], ah[mt], bl0, bl1);
                    mma16816(acc[mt][nt], al2[mt], bh0, bh1);
                }
            }
        }
    }

    // ---------------- epilogue ------------------------------------------------
#pragma unroll
    for (int mt = 0; mt < 2; mt++) {
        int r = rowBase + wm * 32 + mt * 16 + (l >> 2);
#pragma unroll
        for (int nt = 0; nt < 8; nt++) {
            int colb = wn * 64 + nt * 8 + 2 * (l & 3);
            float b0v = sBias[colb], b1v = sBias[colb + 1];
#pragma unroll
            for (int half = 0; half < 2; half++) {
                int rr = r + half * 8;
                if (rr >= M) continue;
                float v0 = acc[mt][nt][half * 2 + 0] + b0v;
                float v1 = acc[mt][nt][half * 2 + 1] + b1v;
                if (mode == 1) { v0 = fmaxf(v0, 0.f); v1 = fmaxf(v1, 0.f); }
                size_t idx = (size_t)rr * 256 + colb;
                *(float2*)(C + idx) = make_float2(v0, v1);
                if (mode == 2) {
                    float2 m = *(const float2*)(muIn + idx);
                    uint2 r0 = threefry2x32(0u, 1u, 0u, (uint32_t)idx);
                    uint2 r1 = threefry2x32(0u, 1u, 0u, (uint32_t)idx + 1u);
                    float z0 = m.x + expf(v0) * bits_to_eps(r0.x ^ r0.y);
                    float z1 = m.y + expf(v1) * bits_to_eps(r1.x ^ r1.y);
                    *(float2*)(zOut + idx) = make_float2(z0, z1);
                }
            }
        }
    }
}

// ---------------- launch ------------------------------------------------------
extern "C" void kernel_launch(void* const* d_in, const int* in_sizes, int n_in,
                              void* d_out, int out_size) {
    const float* x   = (const float*)d_in[0];
    const int*   ei  = (const int*)d_in[1];
    const float* W1  = (const float*)d_in[2];
    const float* b1  = (const float*)d_in[3];
    const float* Wmu = (const float*)d_in[4];
    const float* bmu = (const float*)d_in[5];
    const float* Wls = (const float*)d_in[6];
    const float* bls = (const float*)d_in[7];
    int E = in_sizes[1] / 2;

    float* out = (float*)d_out;
    float* z   = out;
    float* mu  = out + (size_t)NH;
    float* ls  = out + 2 * (size_t)NH;

    float* buf1; float* buf2; int* degp; void* bhp; void* blp;
    cudaGetSymbolAddress((void**)&buf1, g_buf1);
    cudaGetSymbolAddress((void**)&buf2, g_buf2);
    cudaGetSymbolAddress((void**)&degp, g_deg);
    cudaGetSymbolAddress(&bhp, g_Bh);
    cudaGetSymbolAddress(&blp, g_Bl);
    const uint32_t* Bh = (const uint32_t*)bhp;
    const uint32_t* Bl = (const uint32_t*)blp;

    cudaFuncSetAttribute(k_gemm_mma,
                         cudaFuncAttributeMaxDynamicSharedMemorySize, SMEM_MMA);

    // graph prep
    cudaMemsetAsync(degp, 0, N_NODES * sizeof(int));
    k_convW<<<384, 256>>>(W1, Wmu, Wls);
    k_count_deg<<<(E + 255) / 256, 256>>>(ei, E);
    k_scan1<<<NB_SCAN, 1024>>>();
    k_scan2<<<NB_SCAN, 1024>>>(E);
    k_fill<<<(E + 255) / 256, 256>>>(ei, E);

    dim3 gspmm((N_NODES + 7) / 8);

    // t = A_norm @ x -> buf1
    k_spmm_csr<<<gspmm, 256>>>(x, buf1);
    // h = relu(t @ W1 + b1) -> buf2
    k_gemm_mma<<<NBLK_M, 256, SMEM_MMA>>>(buf1, N_NODES, Bh, Bl, b1,
                                          buf2, 1, nullptr, nullptr);
    // p = A_norm @ h -> buf1
    k_spmm_csr<<<gspmm, 256>>>(buf2, buf1);
    // mu
    k_gemm_mma<<<NBLK_M, 256, SMEM_MMA>>>(buf1, N_NODES, Bh + 32768, Bl + 32768,
                                          bmu, mu, 0, nullptr, nullptr);
    // ls + fused z
    k_gemm_mma<<<NBLK_M, 256, SMEM_MMA>>>(buf1, N_NODES, Bh + 65536, Bl + 65536,
                                          bls, ls, 2, mu, z);
}